// round 5
// baseline (speedup 1.0000x reference)
#include <cuda_runtime.h>
#include <cuda_bf16.h>
#include <cstdint>
#include <cstddef>

// ---------------------------------------------------------------------------
// BiLSTM-NER, Round 4:
//  * lstm_persist: flag-array grid barrier (no atomic contention), 8 warps
//    with K-split + SMEM combine, tanh.approx pointwise, load reordering.
//  * FF GEMMs / CRF unchanged from R3 (HMMA mma.sync path).
// ---------------------------------------------------------------------------

#define Tt 256
#define Bb 256
#define Hh 384
#define G4 1536   // 4*H
#define INP 100
#define Kc 10
#define NCTA_LSTM 96

typedef __nv_bfloat16 bf16;

// ============================ PTX helpers ==================================
__device__ __forceinline__ uint32_t smem_to_u32(const void* p) {
    uint32_t a;
    asm("{ .reg .u64 t; cvta.to.shared.u64 t, %1; cvt.u32.u64 %0, t; }"
        : "=r"(a) : "l"(p));
    return a;
}
__device__ __forceinline__ void ldsm4(uint32_t* r, uint32_t saddr) {
    asm volatile("ldmatrix.sync.aligned.m8n8.x4.shared.b16 {%0,%1,%2,%3}, [%4];"
        : "=r"(r[0]), "=r"(r[1]), "=r"(r[2]), "=r"(r[3]) : "r"(saddr));
}
__device__ __forceinline__ void mma_bf16(float* c, const uint32_t* a, const uint32_t* b) {
    asm volatile(
        "mma.sync.aligned.m16n8k16.row.col.f32.bf16.bf16.f32 "
        "{%0,%1,%2,%3}, {%4,%5,%6,%7}, {%8,%9}, {%0,%1,%2,%3};"
        : "+f"(c[0]), "+f"(c[1]), "+f"(c[2]), "+f"(c[3])
        : "r"(a[0]), "r"(a[1]), "r"(a[2]), "r"(a[3]), "r"(b[0]), "r"(b[1]));
}
#define CP_ASYNC16(sa, ga) \
    asm volatile("cp.async.cg.shared.global [%0], [%1], 16;" \
                 :: "r"(sa), "l"(ga) : "memory")
#define CP_COMMIT() asm volatile("cp.async.commit_group;" ::: "memory")
#define CP_WAIT0()  asm volatile("cp.async.wait_group 0;" ::: "memory")

__device__ __forceinline__ float tanh_ap(float x) {
    float y; asm("tanh.approx.f32 %0, %1;" : "=f"(y) : "f"(x)); return y;
}
__device__ __forceinline__ float sig_ap(float x) {
    return fmaf(tanh_ap(0.5f * x), 0.5f, 0.5f);
}

// ------------------------- scratch (device globals) ------------------------
__device__ float g_xw[(size_t)Tt * Bb * G4];       // gate pre-activations (fp32)
__device__ bf16  g_xb[(size_t)Tt * Bb * 128];      // x padded to K=128, bf16
__device__ bf16  g_h0b[(size_t)Tt * Bb * Hh];      // layer0 outputs (bf16)
__device__ bf16  g_h1b[(size_t)Tt * Bb * Hh];      // layer1 outputs (bf16)
__device__ bf16  g_m1b[(size_t)Tt * Bb * 512];     // MLP hidden 1 (bf16)
__device__ bf16  g_m2b[(size_t)Tt * Bb * 1024];    // MLP hidden 2 (bf16)
__device__ float g_em[(size_t)Tt * Bb * Kc];       // emissions (fp32)
__device__ bf16  g_wih0b[1536 * 128];              // Wih0 padded K=128
__device__ bf16  g_wih1b[1536 * 384];
__device__ bf16  g_w1b[512 * 384];
__device__ bf16  g_w2b[1024 * 512];
__device__ bf16  g_h0buf[2 * Bb * Hh];             // recurrent h state (bf16)
__device__ bf16  g_h1buf[2 * Bb * Hh];
__device__ float g_partial[Bb];

__device__ unsigned int g_arrive[NCTA_LSTM];       // flag-array barrier

// ------------------------------ init state --------------------------------
__global__ void init_state_kernel() {
    int i = blockIdx.x * blockDim.x + threadIdx.x;
    if (i < 2 * Bb * Hh) {
        g_h0buf[i] = __float2bfloat16(0.f);
        g_h1buf[i] = __float2bfloat16(0.f);
    }
    if (i < NCTA_LSTM) g_arrive[i] = 0u;
}

// ------------------------------ conversions --------------------------------
__global__ void conv_bf16_kernel(const float* __restrict__ in,
                                 bf16* __restrict__ out, int n2)
{
    int i = blockIdx.x * blockDim.x + threadIdx.x;
    if (i < n2) {
        float2 v = ((const float2*)in)[i];
        ((__nv_bfloat162*)out)[i] = __floats2bfloat162_rn(v.x, v.y);
    }
}
__global__ void conv_pad_kernel(const float* __restrict__ in,
                                bf16* __restrict__ out,
                                int rows, int kin, int kout)
{
    int i = blockIdx.x * blockDim.x + threadIdx.x;
    int total = rows * kout;
    if (i < total) {
        int r = i / kout;
        int c = i - r * kout;
        out[i] = (c < kin) ? __float2bfloat16(in[(size_t)r * kin + c])
                           : __float2bfloat16(0.f);
    }
}

// --------------------- flag-array grid barrier -----------------------------
// Arrival: each CTA's thread0 stores its generation to a private slot
// (no atomic contention). Completion: warp0 of EVERY CTA polls all slots.
__device__ __forceinline__ void grid_barrier(unsigned int gen) {
    __threadfence();
    __syncthreads();
    if (threadIdx.x == 0)
        *(volatile unsigned int*)&g_arrive[blockIdx.x] = gen;
    if (threadIdx.x < 32) {
#pragma unroll
        for (int i = threadIdx.x; i < NCTA_LSTM; i += 32)
            while (*(volatile unsigned int*)&g_arrive[i] < gen) { }
    }
    __syncthreads();
}

// ======================== HMMA feed-forward GEMM ===========================
__global__ __launch_bounds__(256) void mma_gemm(
    const bf16* __restrict__ A, const bf16* __restrict__ B,
    const float* __restrict__ bias1, const float* __restrict__ bias2,
    float* __restrict__ Cf, bf16* __restrict__ Cb,
    int M, int N, int K)
{
    __shared__ __align__(16) bf16 smA[2][128 * 40];
    __shared__ __align__(16) bf16 smB[2][128 * 40];

    const int tid = threadIdx.x;
    const int lane = tid & 31;
    const int wid = tid >> 5;
    const int wm = wid & 3;
    const int wn = wid >> 2;
    const int m0 = blockIdx.y * 128;
    const int n0 = blockIdx.x * 128;

    const uint32_t saddrA[2] = { smem_to_u32(smA[0]), smem_to_u32(smA[1]) };
    const uint32_t saddrB[2] = { smem_to_u32(smB[0]), smem_to_u32(smB[1]) };

    float acc[2][8][4];
#pragma unroll
    for (int i = 0; i < 2; i++)
#pragma unroll
        for (int j = 0; j < 8; j++)
#pragma unroll
            for (int q = 0; q < 4; q++) acc[i][j][q] = 0.f;

    const uint32_t a_off =
        (uint32_t)(((wm * 32 + (lane & 15)) * 40 + (lane >> 4) * 8) * 2);
    uint32_t b_off[4];
#pragma unroll
    for (int jp = 0; jp < 4; jp++)
        b_off[jp] = (uint32_t)(((wn * 64 + jp * 16 + (lane & 7) + ((lane >> 4) << 3)) * 40
                                + ((lane >> 3) & 1) * 8) * 2);

    const int lrow = tid >> 2;
    const int lc   = tid & 3;

    const int nkt = K >> 5;
#pragma unroll
    for (int it = 0; it < 2; it++) {
        int row = lrow + it * 64;
        uint32_t d = (uint32_t)((row * 40 + lc * 8) * 2);
        CP_ASYNC16(saddrA[0] + d, A + (size_t)(m0 + row) * K + lc * 8);
        CP_ASYNC16(saddrB[0] + d, B + (size_t)(n0 + row) * K + lc * 8);
    }
    CP_COMMIT();

    for (int kt = 0; kt < nkt; kt++) {
        CP_WAIT0();
        __syncthreads();
        if (kt + 1 < nkt) {
            int s = (kt + 1) & 1;
            int k0 = (kt + 1) * 32;
#pragma unroll
            for (int it = 0; it < 2; it++) {
                int row = lrow + it * 64;
                uint32_t d = (uint32_t)((row * 40 + lc * 8) * 2);
                CP_ASYNC16(saddrA[s] + d, A + (size_t)(m0 + row) * K + k0 + lc * 8);
                CP_ASYNC16(saddrB[s] + d, B + (size_t)(n0 + row) * K + k0 + lc * 8);
            }
        }
        CP_COMMIT();

        const uint32_t sa = saddrA[kt & 1];
        const uint32_t sb = saddrB[kt & 1];
#pragma unroll
        for (int kk = 0; kk < 2; kk++) {
            uint32_t a[2][4], b[4][4];
            ldsm4(a[0], sa + a_off + kk * 32);
            ldsm4(a[1], sa + a_off + 1280 + kk * 32);
#pragma unroll
            for (int jp = 0; jp < 4; jp++)
                ldsm4(b[jp], sb + b_off[jp] + kk * 32);
#pragma unroll
            for (int mt = 0; mt < 2; mt++)
#pragma unroll
                for (int j = 0; j < 8; j++)
                    mma_bf16(acc[mt][j], a[mt], &b[j >> 1][(j & 1) * 2]);
        }
        __syncthreads();
    }

#pragma unroll
    for (int mt = 0; mt < 2; mt++)
#pragma unroll
        for (int j = 0; j < 8; j++)
#pragma unroll
            for (int p = 0; p < 2; p++) {
                int row = m0 + wm * 32 + mt * 16 + (lane >> 2) + p * 8;
                int col = n0 + wn * 64 + j * 8 + (lane & 3) * 2;
                float bb0 = bias1[col], bb1 = bias1[col + 1];
                if (bias2) { bb0 += bias2[col]; bb1 += bias2[col + 1]; }
                float v0 = acc[mt][j][p * 2] + bb0;
                float v1 = acc[mt][j][p * 2 + 1] + bb1;
                if (Cf) {
                    *(float2*)(Cf + (size_t)row * N + col) = make_float2(v0, v1);
                } else {
                    *(__nv_bfloat162*)(Cb + (size_t)row * N + col) =
                        __floats2bfloat162_rn(v0, v1);
                }
            }
}

// ===================== persistent HMMA LSTM layer ==========================
// 96 CTAs (4 batch x 24 col groups), 256 threads = 8 warps.
// Warps 0-3: K-half 0; warps 4-7: K-half 1 (partials combined via SMEM).
// CTA tile 64 batch x 64 n (n = gate*16 + hcol). Whh slice resident in SMEM.
__global__ __launch_bounds__(256) void lstm_persist(
    const float* __restrict__ Whh, int layer, unsigned int gen_base)
{
    extern __shared__ bf16 dsm[];
    bf16* Wsm = dsm;                          // 64 x 392
    bf16* Asm = dsm + 64 * 392;               // 64 x 392
    float* csm = (float*)(dsm + 2 * 64 * 392);  // 128 x 36 fp32 combine buf
    const uint32_t wbase = smem_to_u32(Wsm);
    const uint32_t abase = smem_to_u32(Asm);

    const int tid = threadIdx.x;
    const int lane = tid & 31;
    const int wid = tid >> 5;
    const int w4 = wid & 3;
    const int grp = wid >> 2;                 // K-half
    const int bx = blockIdx.x & 3;
    const int by = blockIdx.x >> 2;
    const int b0 = bx * 64;
    const int c0 = by * 16;

    // resident W slice: Wsm[n][k], n = g*16+hc  <-  Whh[g*384 + c0+hc][k]
    for (int idx = tid; idx < 64 * 384; idx += 256) {
        int n = idx / 384, k = idx - n * 384;
        int g = n >> 4, hc = n & 15;
        Wsm[n * 392 + k] = __float2bfloat16(Whh[(size_t)(g * Hh + c0 + hc) * Hh + k]);
    }

    bf16* hbuf  = layer ? g_h1buf : g_h0buf;
    bf16* houtL = layer ? g_h1b : g_h0b;

    float cst[8];
#pragma unroll
    for (int i = 0; i < 8; i++) cst[i] = 0.f;

    const uint32_t a_off =
        (uint32_t)(((w4 * 16 + (lane & 15)) * 392 + (lane >> 4) * 8) * 2);
    uint32_t b_off[4];
#pragma unroll
    for (int jp = 0; jp < 4; jp++)
        b_off[jp] = (uint32_t)(((jp * 16 + (lane & 7) + ((lane >> 4) << 3)) * 392
                                + ((lane >> 3) & 1) * 8) * 2);

    const int cidx = (w4 * 32 + lane) * 36;   // combine-buffer base (padded)

    grid_barrier(gen_base + 1);   // all Wsm resident; h phase-0 zeros visible

    for (int t = 0; t < Tt; t++) {
        const int phase = t & 1;
        const bf16* hprev = hbuf + (size_t)phase * Bb * Hh;
        bf16* hnext       = hbuf + (size_t)(phase ^ 1) * Bb * Hh;
        bf16* houtp       = houtL + (size_t)t * Bb * Hh;
        const float* xw   = g_xw + (size_t)t * Bb * G4;

        // ---- issue h tile (64 x 384 bf16) cp.async
#pragma unroll
        for (int it = 0; it < 12; it++) {
            int idx = tid + it * 256;
            int row = idx / 48, c = idx - row * 48;
            CP_ASYNC16(abase + (uint32_t)((row * 392 + c * 8) * 2),
                       hprev + (size_t)(b0 + row) * Hh + c * 8);
        }
        CP_COMMIT();

        // ---- issue xw prefetch (grp0 only; consumed in epilogue; DRAM
        //      latency hides under the cp.async wait + mma loop)
        float2 xv[8][2];
        if (grp == 0) {
#pragma unroll
            for (int j = 0; j < 8; j++)
#pragma unroll
                for (int p = 0; p < 2; p++) {
                    int brow = b0 + w4 * 16 + (lane >> 2) + p * 8;
                    int col = (j >> 1) * Hh + c0 + ((j & 1) << 3) + (lane & 3) * 2;
                    xv[j][p] = *(const float2*)(xw + (size_t)brow * G4 + col);
                }
        }

        CP_WAIT0();
        __syncthreads();

        // ---- gates partial = h_prev @ Whh^T over this warp-group's K half
        float acc[8][4];
#pragma unroll
        for (int j = 0; j < 8; j++)
#pragma unroll
            for (int q = 0; q < 4; q++) acc[j][q] = 0.f;

#pragma unroll
        for (int kk2 = 0; kk2 < 12; kk2++) {
            uint32_t koff = (uint32_t)((grp * 12 + kk2) * 32);   // 16 bf16 = 32B
            uint32_t a[4], b[4][4];
            ldsm4(a, abase + a_off + koff);
#pragma unroll
            for (int jp = 0; jp < 4; jp++)
                ldsm4(b[jp], wbase + b_off[jp] + koff);
#pragma unroll
            for (int j = 0; j < 8; j++)
                mma_bf16(acc[j], a, &b[j >> 1][(j & 1) * 2]);
        }

        // ---- combine K halves through SMEM
        if (grp == 1) {
#pragma unroll
            for (int j = 0; j < 8; j++)
                *(float4*)&csm[cidx + j * 4] =
                    make_float4(acc[j][0], acc[j][1], acc[j][2], acc[j][3]);
        }
        __syncthreads();

        if (grp == 0) {
#pragma unroll
            for (int j = 0; j < 8; j++) {
                float4 v = *(const float4*)&csm[cidx + j * 4];
                acc[j][0] += v.x; acc[j][1] += v.y;
                acc[j][2] += v.z; acc[j][3] += v.w;
            }

            // ---- pointwise LSTM update
#pragma unroll
            for (int p = 0; p < 2; p++) {
                int brow = b0 + w4 * 16 + (lane >> 2) + p * 8;
#pragma unroll
                for (int hb = 0; hb < 2; hb++) {
                    float hnv[2];
#pragma unroll
                    for (int q = 0; q < 2; q++) {
                        float xi = q ? xv[0 + hb][p].y : xv[0 + hb][p].x;
                        float xf = q ? xv[2 + hb][p].y : xv[2 + hb][p].x;
                        float xg = q ? xv[4 + hb][p].y : xv[4 + hb][p].x;
                        float xo = q ? xv[6 + hb][p].y : xv[6 + hb][p].x;
                        float i_ = sig_ap(acc[0 + hb][p * 2 + q] + xi);
                        float f_ = sig_ap(acc[2 + hb][p * 2 + q] + xf);
                        float g_ = tanh_ap(acc[4 + hb][p * 2 + q] + xg);
                        float o_ = sig_ap(acc[6 + hb][p * 2 + q] + xo);
                        int ci = p * 4 + hb * 2 + q;
                        float cn = f_ * cst[ci] + i_ * g_;
                        cst[ci] = cn;
                        hnv[q] = o_ * tanh_ap(cn);
                    }
                    int cg = c0 + hb * 8 + (lane & 3) * 2;
                    __nv_bfloat162 hh = __floats2bfloat162_rn(hnv[0], hnv[1]);
                    *(__nv_bfloat162*)(hnext + (size_t)brow * Hh + cg) = hh;
                    *(__nv_bfloat162*)(houtp + (size_t)brow * Hh + cg) = hh;
                }
            }
        }

        grid_barrier(gen_base + 2 + t);
    }
}

// ------------------------- emissions (N=10 skinny GEMM) --------------------
__global__ __launch_bounds__(256) void em_kernel(
    const bf16* __restrict__ A, const float* __restrict__ W3,
    const float* __restrict__ b3, float* __restrict__ em)
{
    int row  = blockIdx.x * (blockDim.x >> 5) + (threadIdx.x >> 5);
    int lane = threadIdx.x & 31;
    float acc[Kc];
#pragma unroll
    for (int j = 0; j < Kc; j++) acc[j] = 0.f;
    const __nv_bfloat162* ar = (const __nv_bfloat162*)(A + (size_t)row * 1024);
    for (int k2 = lane; k2 < 512; k2 += 32) {
        float2 a = __bfloat1622float2(ar[k2]);
#pragma unroll
        for (int j = 0; j < Kc; j++) {
            acc[j] += a.x * W3[j * 1024 + 2 * k2] + a.y * W3[j * 1024 + 2 * k2 + 1];
        }
    }
#pragma unroll
    for (int j = 0; j < Kc; j++) {
#pragma unroll
        for (int off = 16; off; off >>= 1)
            acc[j] += __shfl_xor_sync(0xffffffffu, acc[j], off);
    }
    if (lane == 0) {
#pragma unroll
        for (int j = 0; j < Kc; j++) em[(size_t)row * Kc + j] = acc[j] + b3[j];
    }
}

// ------------------------------ CRF ----------------------------------------
__global__ __launch_bounds__(32) void crf_kernel(
    const float* __restrict__ em, const int* __restrict__ tags,
    const float* __restrict__ start_t, const float* __restrict__ end_t,
    const float* __restrict__ trans)
{
    const int bp   = blockIdx.x;
    const int lane = threadIdx.x;
    const float NEG = -1e30f;

    float tr[Kc];
    int cl = (lane < Kc) ? lane : 0;
#pragma unroll
    for (int i = 0; i < Kc; i++) tr[i] = trans[i * Kc + cl];

    float a = (lane < Kc) ? (start_t[lane] + em[((size_t)bp * Tt) * Kc + lane]) : NEG;

    for (int tp = 1; tp < Tt; tp++) {
        float e = (lane < Kc) ? em[((size_t)bp * Tt + tp) * Kc + lane] : 0.f;
        float v[Kc];
        float m = NEG;
#pragma unroll
        for (int i = 0; i < Kc; i++) {
            float ai = __shfl_sync(0xffffffffu, a, i);
            v[i] = ai + tr[i];
            m = fmaxf(m, v[i]);
        }
        float s = 0.f;
#pragma unroll
        for (int i = 0; i < Kc; i++) s += __expf(v[i] - m);
        float an = m + __logf(s) + e;
        a = (lane < Kc) ? an : NEG;
    }

    float z = (lane < Kc) ? (a + end_t[lane]) : NEG;
    float zmax = z;
#pragma unroll
    for (int off = 16; off; off >>= 1)
        zmax = fmaxf(zmax, __shfl_xor_sync(0xffffffffu, zmax, off));
    float zs = (lane < Kc) ? __expf(z - zmax) : 0.f;
#pragma unroll
    for (int off = 16; off; off >>= 1)
        zs += __shfl_xor_sync(0xffffffffu, zs, off);
    float logZ = zmax + __logf(zs);

    if (lane == 0) {
        int prev = tags[(size_t)bp * Tt];
        float score = start_t[prev] + em[((size_t)bp * Tt) * Kc + prev];
        for (int tp = 1; tp < Tt; tp++) {
            int tg = tags[(size_t)bp * Tt + tp];
            score += trans[prev * Kc + tg] + em[((size_t)bp * Tt + tp) * Kc + tg];
            prev = tg;
        }
        score += end_t[prev];
        g_partial[bp] = logZ - score;
    }
}

__global__ __launch_bounds__(256) void reduce_kernel(float* __restrict__ out)
{
    __shared__ float sh[256];
    int i = threadIdx.x;
    sh[i] = g_partial[i];
    __syncthreads();
#pragma unroll
    for (int s = 128; s; s >>= 1) {
        if (i < s) sh[i] += sh[i + s];
        __syncthreads();
    }
    if (i == 0) out[0] = sh[0];
}

// ------------------------------ launch -------------------------------------
extern "C" void kernel_launch(void* const* d_in, const int* in_sizes, int n_in,
                              void* d_out, int out_size)
{
    (void)in_sizes; (void)n_in; (void)out_size;
    const float* x    = (const float*)d_in[0];
    const int*   tags = (const int*)d_in[2];
    const float* Wih0 = (const float*)d_in[3];
    const float* Whh0 = (const float*)d_in[4];
    const float* bih0 = (const float*)d_in[5];
    const float* bhh0 = (const float*)d_in[6];
    const float* Wih1 = (const float*)d_in[7];
    const float* Whh1 = (const float*)d_in[8];
    const float* bih1 = (const float*)d_in[9];
    const float* bhh1 = (const float*)d_in[10];
    const float* W1   = (const float*)d_in[11];
    const float* b1   = (const float*)d_in[12];
    const float* W2   = (const float*)d_in[13];
    const float* b2   = (const float*)d_in[14];
    const float* W3   = (const float*)d_in[15];
    const float* b3   = (const float*)d_in[16];
    const float* st   = (const float*)d_in[17];
    const float* et   = (const float*)d_in[18];
    const float* trn  = (const float*)d_in[19];

    float *xw, *emb;
    bf16 *xb, *h0b, *h1b, *m1b, *m2b, *wih0b, *wih1b, *w1b, *w2b;
    cudaGetSymbolAddress((void**)&xw,    g_xw);
    cudaGetSymbolAddress((void**)&emb,   g_em);
    cudaGetSymbolAddress((void**)&xb,    g_xb);
    cudaGetSymbolAddress((void**)&h0b,   g_h0b);
    cudaGetSymbolAddress((void**)&h1b,   g_h1b);
    cudaGetSymbolAddress((void**)&m1b,   g_m1b);
    cudaGetSymbolAddress((void**)&m2b,   g_m2b);
    cudaGetSymbolAddress((void**)&wih0b, g_wih0b);
    cudaGetSymbolAddress((void**)&wih1b, g_wih1b);
    cudaGetSymbolAddress((void**)&w1b,   g_w1b);
    cudaGetSymbolAddress((void**)&w2b,   g_w2b);

    const int M = Tt * Bb;  // 65536
    // SMEM: Wsm (64x392 bf16) + Asm (64x392 bf16) + combine (128x36 fp32)
    const size_t LSTM_SMEM = (size_t)(2 * 64 * 392) * sizeof(bf16)
                           + (size_t)(128 * 36) * sizeof(float);   // 118784 B
    cudaFuncSetAttribute(lstm_persist, cudaFuncAttributeMaxDynamicSharedMemorySize,
                         (int)LSTM_SMEM);

    init_state_kernel<<<(2 * Bb * Hh + 255) / 256, 256>>>();

    // ---- bf16 conversions (pad K=100 -> 128 for x / Wih0)
    conv_pad_kernel<<<(M * 128 + 255) / 256, 256>>>(x, xb, M, INP, 128);
    conv_pad_kernel<<<(1536 * 128 + 255) / 256, 256>>>(Wih0, wih0b, 1536, INP, 128);
    conv_bf16_kernel<<<(1536 * 384 / 2 + 255) / 256, 256>>>(Wih1, wih1b, 1536 * 384 / 2);
    conv_bf16_kernel<<<(512 * 384 / 2 + 255) / 256, 256>>>(W1, w1b, 512 * 384 / 2);
    conv_bf16_kernel<<<(1024 * 512 / 2 + 255) / 256, 256>>>(W2, w2b, 1024 * 512 / 2);

    // ---- layer 0
    mma_gemm<<<dim3(G4 / 128, M / 128), 256>>>(xb, wih0b, bih0, bhh0, xw, nullptr,
                                               M, G4, 128);
    lstm_persist<<<NCTA_LSTM, 256, LSTM_SMEM>>>(Whh0, 0, 0u);

    // ---- layer 1  (generation counter continues: 257 barriers per layer)
    mma_gemm<<<dim3(G4 / 128, M / 128), 256>>>(h0b, wih1b, bih1, bhh1, xw, nullptr,
                                               M, G4, Hh);
    lstm_persist<<<NCTA_LSTM, 256, LSTM_SMEM>>>(Whh1, 1, 257u);

    // ---- MLP
    mma_gemm<<<dim3(512 / 128, M / 128), 256>>>(h1b, w1b, b1, nullptr, nullptr, m1b,
                                                M, 512, Hh);
    mma_gemm<<<dim3(1024 / 128, M / 128), 256>>>(m1b, w2b, b2, nullptr, nullptr, m2b,
                                                 M, 1024, 512);
    em_kernel<<<M / 8, 256>>>(m2b, W3, b3, emb);

    // ---- CRF + reduction
    crf_kernel<<<Bb, 32>>>(emb, tags, st, et, trn);
    reduce_kernel<<<1, 256>>>((float*)d_out);
}